// round 15
// baseline (speedup 1.0000x reference)
#include <cuda_runtime.h>
#include <cstdint>

// Problem constants (IN_SHAPE = (32,3,512,512), OUT_HW = 256, scale 0.5)
#define N_PLANES   96          // N*C
#define IN_HW      512
#define OUT_HW     256
#define R_BLK      16          // output rows per CTA
#define OH_BLKS    (OUT_HW / R_BLK)          // 16
#define RUN        8           // sequential rows per warp run
#define TAPS       8
#define FULLM      0xffffffffu

// Scratch for the generic two-pass fallback only (~50 MB, static => legal).
__device__ float g_scratch[(size_t)N_PLANES * IN_HW * OUT_HW];

// ===========================================================================
// FUSED kernel, V-FIRST + sliding window (taps == 8).
// One CTA per (plane, 16-output-row block).
//
// V-pass: warp = (column chunk q = wid&3, run half = wid>>2). Each warp walks
// 8 SEQUENTIAL output rows keeping the 8 tap input-rows in a float4 register
// window. Stride-2 tap windows mean consecutive oh usually share 6 rows:
// detected at runtime (lanes 0..7 hold this step's fov2 entries; __all_sync
// compares against the previous step's, shifted by 2). On match: shift
// window, load 2 new rows (amortized 2.75 LDG.128/row). Else: full reload.
// Weights/row-offsets broadcast from lanes 0..7 via __shfl_sync.
// Intermediate rows written to smem DEINTERLEAVED (even cols [0,256), odd
// [256,512)) -> W-pass stride-2 gathers are conflict-free.
//
// W-pass: thread t owns output column t; tables loaded once per CTA into
// registers (now amortized over 16 rows); gathers on 16 intermediate rows.
// ===========================================================================
__global__ void __launch_bounds__(256, 4)
fused_resize_kernel(const float* __restrict__ in,
                    const float* __restrict__ w2, const int* __restrict__ fov2,
                    const float* __restrict__ w3, const int* __restrict__ fov3,
                    float* __restrict__ out)
{
    __shared__ float inter[R_BLK * IN_HW];     // 16 x 512 floats = 32 KB

    const int t     = threadIdx.x;
    const int lane  = t & 31;
    const int wid   = t >> 5;
    const int plane = blockIdx.x >> 4;                 // / OH_BLKS
    const int oh0   = (blockIdx.x & (OH_BLKS - 1)) * R_BLK;

    // ---- V-pass: sliding register window over 8 sequential output rows ----
    {
        const int q    = wid & 3;                      // column chunk
        const int half = wid >> 2;                     // which 8-oh run
        const int c4   = lane + 32 * q;                // float4 column
        const char* pc = reinterpret_cast<const char*>(
                             in + (size_t)plane * IN_HW * IN_HW)
                         + (size_t)c4 * 16;

        float4 v[TAPS];
        int f = 0;                                     // lane<8: prev fov2 entry

#pragma unroll
        for (int s = 0; s < RUN; ++s) {
            const int ohl = half * RUN + s;
            const int oh  = oh0 + ohl;

            // lanes 0..7 fetch this oh's table entries
            int nf = 0; float nw = 0.0f;
            if (lane < TAPS) {
                nf = __ldg(fov2 + lane * OUT_HW + oh);
                nw = __ldg(w2   + lane * OUT_HW + oh);
            }

            // window-shift test: nf[j] == f[j+2] for j = 0..5 (warp-uniform)
            bool ok = false;
            if (s > 0) {
                const int fj2 = __shfl_sync(FULLM, f, (lane + 2) & 31);
                ok = __all_sync(FULLM, (lane >= 6) | (nf == fj2));
            }

            if (ok) {
#pragma unroll
                for (int j = 0; j < 6; ++j) v[j] = v[j + 2];
                const unsigned o6 = (unsigned)__shfl_sync(FULLM, nf, 6) * (IN_HW * 4u);
                const unsigned o7 = (unsigned)__shfl_sync(FULLM, nf, 7) * (IN_HW * 4u);
                v[6] = __ldg(reinterpret_cast<const float4*>(pc + o6));
                v[7] = __ldg(reinterpret_cast<const float4*>(pc + o7));
            } else {
#pragma unroll
                for (int j = 0; j < TAPS; ++j) {
                    const unsigned oj =
                        (unsigned)__shfl_sync(FULLM, nf, j) * (IN_HW * 4u);
                    v[j] = __ldg(reinterpret_cast<const float4*>(pc + oj));
                }
            }
            f = nf;

            float4 a = make_float4(0.f, 0.f, 0.f, 0.f);
#pragma unroll
            for (int j = 0; j < TAPS; ++j) {
                const float wj = __shfl_sync(FULLM, nw, j);
                a.x = fmaf(wj, v[j].x, a.x);
                a.y = fmaf(wj, v[j].y, a.y);
                a.z = fmaf(wj, v[j].z, a.z);
                a.w = fmaf(wj, v[j].w, a.w);
            }

            // deinterleaved store: elems 4c4..4c4+3 -> even/odd phase pairs
            float* ev = inter + ohl * IN_HW;
            reinterpret_cast<float2*>(ev)[c4]       = make_float2(a.x, a.z);
            reinterpret_cast<float2*>(ev + 256)[c4] = make_float2(a.y, a.w);
        }
    }
    __syncthreads();

    // ---- W-pass: thread t owns output column ow = t ---------------------
    {
        float wr[TAPS];
        int   pr[TAPS];                                // deinterleaved position
#pragma unroll
        for (int j = 0; j < TAPS; ++j) {
            wr[j] = __ldg(w3 + j * OUT_HW + t);
            const int idx = __ldg(fov3 + j * OUT_HW + t);
            pr[j] = (idx >> 1) + ((idx & 1) << 8);
        }
        float* op = out + (size_t)plane * OUT_HW * OUT_HW
                        + (size_t)oh0 * OUT_HW + t;
#pragma unroll
        for (int r = 0; r < R_BLK; ++r) {
            const float* rb = inter + r * IN_HW;
            float s0 = 0.f, s1 = 0.f;
#pragma unroll
            for (int j = 0; j < TAPS; j += 2) {
                s0 = fmaf(wr[j],     rb[pr[j]],     s0);
                s1 = fmaf(wr[j + 1], rb[pr[j + 1]], s1);
            }
            op[r * OUT_HW] = s0 + s1;                  // coalesced per warp
        }
    }
}

// ===========================================================================
// Generic two-pass fallback (any taps).
// ===========================================================================
__global__ void __launch_bounds__(OUT_HW)
hpass_kernel(const float* __restrict__ in, const float* __restrict__ w,
             const int* __restrict__ fov, float* __restrict__ out1, int taps)
{
    __shared__ float row[IN_HW];
    const int r = blockIdx.x;
    const int t = threadIdx.x;
    const float2* src2 = reinterpret_cast<const float2*>(in + (size_t)r * IN_HW);
    reinterpret_cast<float2*>(row)[t] = src2[t];
    __syncthreads();
    float sum = 0.0f;
    for (int j = 0; j < taps; ++j) {
        const int i = j * OUT_HW + t;
        sum = fmaf(__ldg(w + i), row[__ldg(fov + i)], sum);
    }
    out1[(size_t)r * OUT_HW + t] = sum;
}

__global__ void __launch_bounds__(256)
vpass_kernel(const float* __restrict__ s, const float* __restrict__ w,
             const int* __restrict__ fov, float4* __restrict__ out, int taps)
{
    const int idx = blockIdx.x * blockDim.x + threadIdx.x;
    const int ow4 = idx & 63;
    const int oh  = (idx >> 6) & (OUT_HW - 1);
    const int pl  = idx >> 14;
    const float4* base =
        reinterpret_cast<const float4*>(s + (size_t)pl * IN_HW * OUT_HW) + ow4;
    float4 acc = make_float4(0.f, 0.f, 0.f, 0.f);
    for (int j = 0; j < taps; ++j) {
        const int i = j * OUT_HW + oh;
        const float wj = __ldg(w + i);
        const float4 v = base[(size_t)__ldg(fov + i) * (OUT_HW / 4)];
        acc.x = fmaf(wj, v.x, acc.x);
        acc.y = fmaf(wj, v.y, acc.y);
        acc.z = fmaf(wj, v.z, acc.z);
        acc.w = fmaf(wj, v.w, acc.w);
    }
    out[idx] = acc;
}

// ===========================================================================
// Inputs (metadata order): in_tensor f32, w2 f32, fov2 i32, w3 f32, fov3 i32.
// ===========================================================================
extern "C" void kernel_launch(void* const* d_in, const int* in_sizes, int n_in,
                              void* d_out, int out_size)
{
    const float* in   = (const float*)d_in[0];
    const float* w2   = (const float*)d_in[1];
    const int*   fov2 = (const int*)  d_in[2];
    const float* w3   = (const float*)d_in[3];
    const int*   fov3 = (const int*)  d_in[4];

    const int taps = in_sizes[2] / OUT_HW;

    if (taps == TAPS) {
        fused_resize_kernel<<<N_PLANES * OH_BLKS, 256>>>(
            in, w2, fov2, w3, fov3, (float*)d_out);
    } else {
        float* scratch = nullptr;
        cudaGetSymbolAddress((void**)&scratch, g_scratch);
        hpass_kernel<<<N_PLANES * IN_HW, OUT_HW>>>(in, w3, fov3, scratch, taps);
        const int n_vec4 = N_PLANES * OUT_HW * OUT_HW / 4;
        vpass_kernel<<<n_vec4 / 256, 256>>>(scratch, w2, fov2, (float4*)d_out, taps);
    }
}